// round 17
// baseline (speedup 1.0000x reference)
#include <cuda_runtime.h>
#include <cuda_fp16.h>
#include <math.h>
#include <stdint.h>

// ---------------- problem constants ----------------
#define B_  32
#define L_  1024
#define DIN 16
#define DM  512
#define DI  1024          // EXP*DM
#define H_  16            // DI/P
#define P_  64
#define N_  64
#define DCONV 4
#define CONV_DIM 1152     // DI + 2N
#define DPROJ 2192        // 2*DI + 2*N + H
#define REST 1168         // CONV_DIM + H
#define NCLS 10
#define BL  (B_*L_)       // 32768
#define EPS 1e-5f

// fragment-ordered weight buffer sizes (words): T * NBLK * 2048
#define W2F_WORDS  (4  * 2  * 2048)
#define W3F_WORDS  (8  * 4  * 2048)
#define WINF_WORDS (16 * 10 * 2048)

// ---------------- scratch (static device globals; no allocations) -------------
__device__ uint32_t g_h2h[(size_t)BL*128];   // [BL][128]
__device__ uint32_t g_uh [(size_t)BL*256];   // [BL][256]
// packed half2 weights in staged-fragment order
__device__ uint32_t g_w2f[W2F_WORDS];
__device__ uint32_t g_w3f[W3F_WORDS];
__device__ uint32_t g_winf[WINF_WORDS];
// fp32 intermediates
__device__ float g_xbcr[(size_t)BL*REST];
__device__ float g_Bm [BL*N_];
__device__ float g_Cm [B_*N_];
__device__ float g_dtp[B_*H_*L_];
__device__ float g_beta[BL];
__device__ float g_wbuf[B_*H_*L_];           // w = coef*beta
__device__ int   g_need [B_*H_*8];           // per (bh, chunk) compute flag
__device__ float g_y  [B_*DI];
__device__ float g_z  [B_*DI];

// ---------------- helpers ------------------------------------------------------
__device__ __forceinline__ uint32_t pack_h2(float a, float b) {
    __half2 h = __floats2half2_rn(a, b);
    return *(uint32_t*)&h;
}
__device__ __forceinline__ void mma_f16(float* c, const uint32_t* a, const uint32_t* b) {
    asm volatile(
        "mma.sync.aligned.m16n8k16.row.col.f32.f16.f16.f32 "
        "{%0,%1,%2,%3}, {%4,%5,%6,%7}, {%8,%9}, {%0,%1,%2,%3};\n"
        : "+f"(c[0]), "+f"(c[1]), "+f"(c[2]), "+f"(c[3])
        : "r"(a[0]), "r"(a[1]), "r"(a[2]), "r"(a[3]), "r"(b[0]), "r"(b[1]));
}
__device__ __forceinline__ void ldmx4(uint32_t& r0, uint32_t& r1, uint32_t& r2, uint32_t& r3,
                                      uint32_t saddr) {
    asm volatile("ldmatrix.sync.aligned.m8n8.x4.shared.b16 {%0,%1,%2,%3}, [%4];"
                 : "=r"(r0), "=r"(r1), "=r"(r2), "=r"(r3) : "r"(saddr));
}
__device__ __forceinline__ void cp16(uint32_t saddr, const void* g) {
    asm volatile("cp.async.cg.shared.global [%0], [%1], 16;\n" :: "r"(saddr), "l"(g));
}
__device__ __forceinline__ void cp_commit() { asm volatile("cp.async.commit_group;\n"); }
template<int n> __device__ __forceinline__ void cp_wait() {
    asm volatile("cp.async.wait_group %0;\n" :: "n"(n));
}
__device__ __forceinline__ uint32_t smem_u32(const void* p) {
    uint32_t a;
    asm("{ .reg .u64 t; cvta.to.shared.u64 t, %1; cvt.u32.u64 %0, t; }" : "=r"(a) : "l"(p));
    return a;
}

#define STG 6
#define AW 2048
#define BW 2048
#define SMEM_BYTES (STG * (AW + BW) * 4)   // 98304; x2 CTAs = 192KB <= 227KB
#define G12_SMEM ((8 * 2048) * 4 + (2048 + 2048 + 128) * 4)   // 82432

// =============================================================================
// FP16 tensor-core GEMM (m16n8k16, fp32 accum), cp.async 6-stage pipeline,
// two tiles per barrier (T even; call sites have T in {8,16}).
// bn0 = n-block offset; need = optional per-(bh,chunk) flag array: block
// (b,chunk,nb) runs iff any of need[(b*16+nb*2+{0,1})*8 + {chunk, chunk+1}].
// =============================================================================
template<int RELU, int OUTH>
__global__ __launch_bounds__(256, 2) void hgemm_kernel(
    const uint32_t* __restrict__ A, int lda,
    const uint32_t* __restrict__ Wf, int NBLK,
    const float* __restrict__ bias,
    float* __restrict__ C, int ldc,
    int N, int Kh, int bn0, const int* __restrict__ need)
{
    if (need) {
        int b = blockIdx.y >> 3, chunk = blockIdx.y & 7;
        int h0 = blockIdx.x * 2;
        int v = need[(b * 16 + h0) * 8 + chunk] | need[(b * 16 + h0 + 1) * 8 + chunk];
        if (chunk < 7)
            v |= need[(b * 16 + h0) * 8 + chunk + 1] | need[(b * 16 + h0 + 1) * 8 + chunk + 1];
        if (!v) return;
    }
    extern __shared__ uint32_t smem[];
    uint32_t* Asm = smem;
    uint32_t* Bsm = smem + STG * AW;

    const int bm = blockIdx.y * 128;
    const int nblk = blockIdx.x + bn0;
    const int bn = nblk * 128;
    const int tid = threadIdx.x;
    const int warp = tid >> 5;
    const int lane = tid & 31;
    const int warp_m = (warp & 1) * 64;
    const int warp_n = (warp >> 1) * 32;
    const int lg = lane >> 2;
    const int lr = lane & 3;

    const int am0 = tid >> 2;
    const int akq = tid & 3;
    const int aw0 = am0 * 16 + ((akq ^ (am0 & 3)) << 2);
    const int am1 = am0 + 64;
    const int aw1 = am1 * 16 + ((akq ^ (am1 & 3)) << 2);

    const int q  = lane >> 3;
    const int rr = lane & 7;
    const int mlo = rr + (q & 1) * 8;
    const int qh = q >> 1;
    uint32_t asw[4][2];
    #pragma unroll
    for (int mi = 0; mi < 4; mi++) {
        int m = warp_m + mi * 16 + mlo;
        #pragma unroll
        for (int ks = 0; ks < 2; ks++)
            asw[mi][ks] = m * 16 + (((ks * 2 + qh) ^ (m & 3)) << 2);
    }
    const uint32_t as_base = smem_u32(Asm);
    const uint32_t bs_base = smem_u32(Bsm);

    float acc[4][4][4];
    #pragma unroll
    for (int i = 0; i < 4; i++)
        #pragma unroll
        for (int j = 0; j < 4; j++)
            #pragma unroll
            for (int r = 0; r < 4; r++) acc[i][j][r] = 0.f;

    const int T = Kh >> 5;

    auto issue = [&](int t) {
        const int s = t % STG;
        const int k0 = t * 16;
        cp16(as_base + (s * AW + aw0) * 4, &A[(size_t)(bm + am0) * lda + k0 + akq * 4]);
        cp16(as_base + (s * AW + aw1) * 4, &A[(size_t)(bm + am1) * lda + k0 + akq * 4]);
        const uint32_t* wsrc = Wf + (size_t)(t * NBLK + nblk) * 2048;
        cp16(bs_base + (s * BW + tid * 4) * 4,          &wsrc[tid * 4]);
        cp16(bs_base + (s * BW + (tid + 256) * 4) * 4,  &wsrc[(tid + 256) * 4]);
        cp_commit();
    };

    auto compute_tile = [&](int t) {
        const int s = t % STG;
        const uint32_t* Bst = Bsm + s * BW;
        #pragma unroll
        for (int ks = 0; ks < 2; ks++) {
            uint32_t af[4][4], bf[4][2];
            #pragma unroll
            for (int mi = 0; mi < 4; mi++)
                ldmx4(af[mi][0], af[mi][1], af[mi][2], af[mi][3],
                      as_base + (s * AW + asw[mi][ks]) * 4);
            #pragma unroll
            for (int ni = 0; ni < 4; ni++) {
                uint2 bv = *(const uint2*)&Bst[ks * 1024 + (warp_n + ni * 8) * 8 + lane * 2];
                bf[ni][0] = bv.x; bf[ni][1] = bv.y;
            }
            #pragma unroll
            for (int mi = 0; mi < 4; mi++)
                #pragma unroll
                for (int ni = 0; ni < 4; ni++)
                    mma_f16(acc[mi][ni], af[mi], bf[ni]);
        }
    };

    #pragma unroll
    for (int i = 0; i < STG - 2; i++) {
        if (i < T) issue(i);
        else       cp_commit();
    }

    for (int t = 0; t < T; t += 2) {
        cp_wait<STG - 4>();
        __syncthreads();
        compute_tile(t);
        compute_tile(t + 1);
        if (t + STG - 2 < T) issue(t + STG - 2); else cp_commit();
        if (t + STG - 1 < T) issue(t + STG - 1); else cp_commit();
    }

    #pragma unroll
    for (int mi = 0; mi < 4; mi++) {
        #pragma unroll
        for (int half = 0; half < 2; half++) {
            const int gr = bm + warp_m + mi * 16 + lg + half * 8;
            #pragma unroll
            for (int ni = 0; ni < 4; ni++) {
                const int gn = bn + warp_n + ni * 8 + lr * 2;
                float v0 = acc[mi][ni][half * 2 + 0];
                float v1 = acc[mi][ni][half * 2 + 1];
                if (bias) { v0 += bias[gn]; v1 += bias[gn + 1]; }
                if (RELU) { v0 = fmaxf(v0, 0.f); v1 = fmaxf(v1, 0.f); }
                if (OUTH) {
                    ((uint32_t*)C)[(size_t)gr * ldc + (gn >> 1)] = pack_h2(v0, v1);
                } else {
                    if (gn >= N) continue;
                    *(float2*)&C[(size_t)gr * ldc + gn] = make_float2(v0, v1);
                }
            }
        }
    }
}

// =============================================================================
// Fused G1+G2: h1 = relu(x@W1+b1) computed IN SMEM (fp32, k-ascending order,
// bit-identical to the old sgemm1), packed straight into the XOR-swizzled A
// stages; then the standard G2 mma mainloop (T=4) reads A from smem while the
// 4 B tiles arrive via cp.async issued at kernel start.
// Output: h2 = relu(h1@W2+b2), packed half2 [BL][128] words.
// =============================================================================
__global__ __launch_bounds__(256, 2) void g12_kernel(
    const float* __restrict__ x,
    const float* __restrict__ W1,
    const float* __restrict__ b1,
    const uint32_t* __restrict__ w2f,    // fragment-ordered, NBLK=2
    const float* __restrict__ b2,
    uint32_t* __restrict__ h2h)
{
    extern __shared__ uint32_t smem[];
    uint32_t* Asm = smem;                        // 4 stages x 2048 words
    uint32_t* Bsm = smem + 4 * 2048;             // 4 stages x 2048 words
    float* xs = (float*)(smem + 8 * 2048);       // 2048 f32
    float* ws = xs + 2048;                       // 2048 f32 (W1 row-major 16x128)
    float* bs = ws + 2048;                       // 128 f32

    const int nblk = blockIdx.x;                 // 0..1
    const int bm = blockIdx.y * 128;
    const int tid = threadIdx.x;
    const int warp = tid >> 5;
    const int lane = tid & 31;
    const int warp_m = (warp & 1) * 64;
    const int warp_n = (warp >> 1) * 32;
    const int lg = lane >> 2;
    const int lr = lane & 3;
    const uint32_t as_base = smem_u32(Asm);
    const uint32_t bs_base = smem_u32(Bsm);

    // issue all 4 B tiles immediately
    #pragma unroll
    for (int t = 0; t < 4; t++) {
        const uint32_t* wsrc = w2f + (size_t)(t * 2 + nblk) * 2048;
        cp16(bs_base + (t * 2048 + tid * 4) * 4,         &wsrc[tid * 4]);
        cp16(bs_base + (t * 2048 + (tid + 256) * 4) * 4, &wsrc[(tid + 256) * 4]);
    }
    cp_commit();

    // stage x tile, W1, b1
    for (int i = tid; i < 2048; i += 256)
        xs[i] = x[(size_t)(bm + (i >> 4)) * DIN + (i & 15)];
    for (int i = tid; i < 2048; i += 256) ws[i] = W1[i];
    if (tid < 128) bs[tid] = b1[tid];
    __syncthreads();

    // phase 1: h1 tile -> A stages (thread: row m = tid>>1, 64 half-cols)
    {
        const int m = tid >> 1;
        const int nh0 = (tid & 1) * 64;
        float xr[16];
        #pragma unroll
        for (int k = 0; k < 16; k++) xr[k] = xs[m * 16 + k];
        #pragma unroll
        for (int w = 0; w < 32; w++) {
            int n0 = nh0 + 2 * w;
            float a0 = 0.f, a1 = 0.f;
            #pragma unroll
            for (int k = 0; k < 16; k++) {
                a0 = fmaf(xr[k], ws[k * 128 + n0],     a0);
                a1 = fmaf(xr[k], ws[k * 128 + n0 + 1], a1);
            }
            a0 = fmaxf(a0 + bs[n0],     0.f);
            a1 = fmaxf(a1 + bs[n0 + 1], 0.f);
            int kp = (nh0 >> 1) + w;          // global pair-word 0..63
            int s = kp >> 4, kq = kp & 15;
            Asm[s * 2048 + m * 16 + (((kq >> 2) ^ (m & 3)) << 2) + (kq & 3)] = pack_h2(a0, a1);
        }
    }
    cp_wait<0>();
    __syncthreads();

    // ldmatrix addressing
    const int q  = lane >> 3;
    const int rr = lane & 7;
    const int mlo = rr + (q & 1) * 8;
    const int qh = q >> 1;
    uint32_t asw[4][2];
    #pragma unroll
    for (int mi = 0; mi < 4; mi++) {
        int m = warp_m + mi * 16 + mlo;
        #pragma unroll
        for (int ks = 0; ks < 2; ks++)
            asw[mi][ks] = m * 16 + (((ks * 2 + qh) ^ (m & 3)) << 2);
    }

    float acc[4][4][4];
    #pragma unroll
    for (int i = 0; i < 4; i++)
        #pragma unroll
        for (int j = 0; j < 4; j++)
            #pragma unroll
            for (int r = 0; r < 4; r++) acc[i][j][r] = 0.f;

    #pragma unroll
    for (int t = 0; t < 4; t++) {
        const uint32_t* Bst = Bsm + t * 2048;
        #pragma unroll
        for (int ks = 0; ks < 2; ks++) {
            uint32_t af[4][4], bf[4][2];
            #pragma unroll
            for (int mi = 0; mi < 4; mi++)
                ldmx4(af[mi][0], af[mi][1], af[mi][2], af[mi][3],
                      as_base + (t * 2048 + asw[mi][ks]) * 4);
            #pragma unroll
            for (int ni = 0; ni < 4; ni++) {
                uint2 bv = *(const uint2*)&Bst[ks * 1024 + (warp_n + ni * 8) * 8 + lane * 2];
                bf[ni][0] = bv.x; bf[ni][1] = bv.y;
            }
            #pragma unroll
            for (int mi = 0; mi < 4; mi++)
                #pragma unroll
                for (int ni = 0; ni < 4; ni++)
                    mma_f16(acc[mi][ni], af[mi], bf[ni]);
        }
    }

    const int bn = nblk * 128;
    #pragma unroll
    for (int mi = 0; mi < 4; mi++) {
        #pragma unroll
        for (int half = 0; half < 2; half++) {
            const int gr = bm + warp_m + mi * 16 + lg + half * 8;
            #pragma unroll
            for (int ni = 0; ni < 4; ni++) {
                const int gn = bn + warp_n + ni * 8 + lr * 2;
                float v0 = fmaxf(acc[mi][ni][half * 2 + 0] + b2[gn],     0.f);
                float v1 = fmaxf(acc[mi][ni][half * 2 + 1] + b2[gn + 1], 0.f);
                h2h[(size_t)gr * 128 + (gn >> 1)] = pack_h2(v0, v1);
            }
        }
    }
}

// ---------------- weight prep: fragment-ordered packing ------------------------
__global__ void prep_kernel(const float* __restrict__ W2,
                            const float* __restrict__ W3,
                            const float* __restrict__ Win)
{
    int i = blockIdx.x * 256 + threadIdx.x;
    if (i < W2F_WORDS) {
        int within = i & 2047, blk = (i >> 11) & 1, t = i >> 12;
        int ks = within >> 10, n = (within >> 3) & 127;
        int lr = (within & 7) >> 1, sub = within & 1;
        int k = 2 * (t * 16 + ks * 8 + lr + sub * 4);
        int col = blk * 128 + n;
        g_w2f[i] = pack_h2(W2[k * 256 + col], W2[(k + 1) * 256 + col]);
    }
    if (i < W3F_WORDS) {
        int within = i & 2047, blk = (i >> 11) & 3, t = i >> 13;
        int ks = within >> 10, n = (within >> 3) & 127;
        int lr = (within & 7) >> 1, sub = within & 1;
        int k = 2 * (t * 16 + ks * 8 + lr + sub * 4);
        int col = blk * 128 + n;
        g_w3f[i] = pack_h2(W3[k * 512 + col], W3[(k + 1) * 512 + col]);
    }
    if (i < WINF_WORDS) {
        int within = i & 2047, blk = (i >> 11) % 10, t = i / (2048 * 10);
        int ks = within >> 10, n = (within >> 3) & 127;
        int lr = (within & 7) >> 1, sub = within & 1;
        int k = 2 * (t * 16 + ks * 8 + lr + sub * 4);
        int col = blk * 128 + n;
        g_winf[i] = (col < REST)
            ? pack_h2(Win[(size_t)k * DPROJ + DI + col],
                      Win[(size_t)(k + 1) * DPROJ + DI + col])
            : 0u;
    }
}

// ---------------- activation helpers ------------------------------------------
__device__ __forceinline__ float siluf(float x) { return x / (1.f + __expf(-x)); }
__device__ __forceinline__ float softplusf(float x) {
    return (x > 0.f) ? x + log1pf(__expf(-x)) : log1pf(__expf(x));
}

// ---------------- conv for B/C/dt channels (144 channels) ----------------------
#define LCH 64
__global__ void conv_kernel(const float* __restrict__ xbcr,
                            const float* __restrict__ conv_w,
                            const float* __restrict__ conv_b,
                            const float* __restrict__ dt_bias,
                            float* __restrict__ Bm,
                            float* __restrict__ Cm, float* __restrict__ dtp)
{
    int c  = DI + threadIdx.x;
    int b  = blockIdx.y;
    int l0 = blockIdx.z * LCH;
    if (c >= REST) return;
    const float* col = xbcr + (size_t)b * L_ * REST + c;

    if (c >= CONV_DIM) {
        int h = c - CONV_DIM;
        float bias = dt_bias[h];
        float* drow = dtp + (size_t)(b * H_ + h) * L_;
        #pragma unroll 8
        for (int l = l0; l < l0 + LCH; l++)
            drow[l] = softplusf(col[(size_t)l * REST] + bias);
        return;
    }
    float w0 = conv_w[c * 4 + 0], w1 = conv_w[c * 4 + 1];
    float w2 = conv_w[c * 4 + 2], w3 = conv_w[c * 4 + 3];
    float cb = conv_b[c];

    if (c >= DI + N_) {
        if (l0 + LCH != L_) return;
        int l = L_ - 1;
        float acc = cb + w0 * col[(size_t)(l - 3) * REST] + w1 * col[(size_t)(l - 2) * REST]
                       + w2 * col[(size_t)(l - 1) * REST] + w3 * col[(size_t)l * REST];
        Cm[b * N_ + (c - DI - N_)] = siluf(acc);
        return;
    }
    float xm3 = (l0 - 3 >= 0) ? col[(size_t)(l0 - 3) * REST] : 0.f;
    float xm2 = (l0 - 2 >= 0) ? col[(size_t)(l0 - 2) * REST] : 0.f;
    float xm1 = (l0 - 1 >= 0) ? col[(size_t)(l0 - 1) * REST] : 0.f;
    float* orow = Bm + (size_t)(b * L_ + l0) * N_ + (c - DI);
    #pragma unroll 8
    for (int l = l0; l < l0 + LCH; l++) {
        float xl = col[(size_t)l * REST];
        float acc = fmaf(w0, xm3, fmaf(w1, xm2, fmaf(w2, xm1, fmaf(w3, xl, cb))));
        *orow = siluf(acc);
        orow += N_;
        xm3 = xm2; xm2 = xm1; xm1 = xl;
    }
}

// ---------------- beta[b,t] = B_t . C_last -------------------------------------
__global__ void beta_kernel(const float* __restrict__ Bm,
                            const float* __restrict__ Cm,
                            float* __restrict__ beta)
{
    int row = blockIdx.x * 8 + (threadIdx.x >> 5);
    int b = row >> 10;
    int lane = threadIdx.x & 31;
    float s = Bm[(size_t)row * N_ + lane]      * Cm[b * N_ + lane]
            + Bm[(size_t)row * N_ + 32 + lane] * Cm[b * N_ + 32 + lane];
    #pragma unroll
    for (int o = 16; o; o >>= 1) s += __shfl_down_sync(0xffffffffu, s, o);
    if (lane == 0) beta[row] = s;
}

// ---------------- fused suffix scan + w = coef*beta + need flags ----------------
__global__ void scanw_kernel(const float* __restrict__ dtp,
                             const float* __restrict__ A_log,
                             const float* __restrict__ beta,
                             float* __restrict__ wbuf,
                             int* __restrict__ need)
{
    int bh = blockIdx.x;
    int h = bh & (H_ - 1);
    int b = bh >> 4;
    float a = expf(A_log[h]);
    __shared__ float part[256];
    __shared__ float off[256];
    const float* row = dtp + (size_t)bh * L_;
    int t0 = threadIdx.x * 4;
    float v0 = row[t0], v1 = row[t0 + 1], v2 = row[t0 + 2], v3 = row[t0 + 3];
    part[threadIdx.x] = v0 + v1 + v2 + v3;
    __syncthreads();
    if (threadIdx.x == 0) {
        float s = 0.f;
        for (int i = 255; i >= 0; i--) { off[i] = s; s += part[i]; }
    }
    __syncthreads();
    float S3 = off[threadIdx.x];
    float S2 = S3 + v3;
    float S1 = S2 + v2;
    float S0 = S1 + v1;
    const float* brow = beta + (size_t)b * L_;
    float w0v = (expf(-a * S0) * v0) * brow[t0 + 0];
    float w1v = (expf(-a * S1) * v1) * brow[t0 + 1];
    float w2v = (expf(-a * S2) * v2) * brow[t0 + 2];
    float w3v = (expf(-a * S3) * v3) * brow[t0 + 3];
    float* wrow = wbuf + (size_t)bh * L_;
    wrow[t0 + 0] = w0v; wrow[t0 + 1] = w1v;
    wrow[t0 + 2] = w2v; wrow[t0 + 3] = w3v;
    int nz = (w0v != 0.f) | (w1v != 0.f) | (w2v != 0.f) | (w3v != 0.f);
    int any = __any_sync(0xffffffffu, nz);
    int c = threadIdx.x >> 5;            // warp c covers t = 128c .. 128c+127
    if ((threadIdx.x & 31) == 0) need[bh * 8 + c] = any | (c == 7);
}

// ---------------- z GEMV -------------------------------------------------------
__global__ void zv_kernel(const uint32_t* __restrict__ uh,
                          const float* __restrict__ Win,
                          float* __restrict__ zb)
{
    int b  = blockIdx.y;
    int n  = blockIdx.x * 128 + threadIdx.x;
    __shared__ float us[DM];
    const uint32_t* urow = uh + (size_t)(b * L_ + L_ - 1) * 256;
    for (int i = threadIdx.x; i < 256; i += 128) {
        __half2 h = *(const __half2*)&urow[i];
        float2 f = __half22float2(h);
        us[2 * i] = f.x; us[2 * i + 1] = f.y;
    }
    __syncthreads();
    float acc = 0.f;
    #pragma unroll 8
    for (int d = 0; d < DM; d++) acc = fmaf(us[d], Win[(size_t)d * DPROJ + n], acc);
    zb[b * DI + n] = acc;
}

// ---------------- fused conv-x + time reduction (chunk + j-block skipping) ------
__global__ void xy_kernel(const float* __restrict__ xbcr,
                          const float* __restrict__ conv_w,
                          const float* __restrict__ conv_b,
                          const float* __restrict__ wbuf,
                          const int* __restrict__ need,
                          const float* __restrict__ D,
                          float* __restrict__ y)
{
    int bh = blockIdx.x;
    int b = bh >> 4, h = bh & (H_ - 1);
    int tid = threadIdx.x;
    int tq = tid >> 6;
    int p  = tid & 63;
    int c  = h * P_ + p;

    __shared__ float w[L_];
    __shared__ float partial[8][64];

    const float* wrow = wbuf + (size_t)bh * L_;
    for (int i = tid; i < L_; i += 512) w[i] = wrow[i];
    __syncthreads();

    float acc = 0.f;
    if (need[bh * 8 + tq]) {
        float w0 = conv_w[c * 4 + 0], w1 = conv_w[c * 4 + 1];
        float w2 = conv_w[c * 4 + 2], w3 = conv_w[c * 4 + 3];
        float cb = conv_b[c];
        const float* col = xbcr + (size_t)b * L_ * REST + c;
        const int t0 = tq * 128;
        float xm3 = (t0 - 3 >= 0) ? col[(size_t)(t0 - 3) * REST] : 0.f;
        float xm2 = (t0 - 2 >= 0) ? col[(size_t)(t0 - 2) * REST] : 0.f;
        float xm1 = (t0 - 1 >= 0) ? col[(size_t)(t0 - 1) * REST] : 0.f;
        float vlast = 0.f;
        for (int j = 0; j < 128; j += 8) {
            float wv[8];
            #pragma unroll
            for (int i = 0; i < 8; i++) wv[i] = w[t0 + j + i];
            bool anyw = (wv[0] != 0.f) | (wv[1] != 0.f) | (wv[2] != 0.f) | (wv[3] != 0.f)
                      | (wv[4] != 0.f) | (wv[5] != 0.f) | (wv[6] != 0.f) | (wv[7] != 0.f);
            bool force = (tq == 7) && (j == 120);
            if (anyw || force) {
                float xv[8];
                #pragma unroll
                for (int i = 0; i < 8; i++)
                    xv[i] = col[(size_t)(t0 + j + i) * REST];
                #pragma unroll
                for (int i = 0; i < 8; i++) {
                    float v = siluf(fmaf(w0, xm3, fmaf(w1, xm2, fmaf(w2, xm1, fmaf(w3, xv[i], cb)))));
                    acc = fmaf(wv[i], v, acc);
                    vlast = v;
                    xm3 = xm2; xm2 = xm1; xm1 = xv[i];
                }
            } else {
                xm3 = col[(size_t)(t0 + j + 5) * REST];
                xm2 = col[(size_t)(t0 + j + 6) * REST];
                xm1 = col[(size_t)(t0 + j + 7) * REST];
            }
        }
        if (tq == 7) acc = fmaf(D[h], vlast, acc);
    }
    partial[tq][p] = acc;
    __syncthreads();
    if (tq == 0) {
        float s = 0.f;
        #pragma unroll
        for (int qi = 0; qi < 8; qi++) s += partial[qi][p];
        y[bh * P_ + p] = s;
    }
}

// ---------------- gate + rmsnorm + Wout + Wc head ------------------------------
__global__ void final_kernel(const float* __restrict__ y,
                             const float* __restrict__ zlast,
                             const float* __restrict__ norm_w,
                             const float* __restrict__ Wout,
                             const float* __restrict__ Wc,
                             const float* __restrict__ bc,
                             float* __restrict__ out)
{
    int b = blockIdx.x;
    int tid = threadIdx.x;
    __shared__ float yn[DI];
    __shared__ float seq[DM];
    __shared__ float red[256];
    float ss = 0.f;
    for (int d = tid; d < DI; d += 256) {
        float z = zlast[b * DI + d];
        float g = y[b * DI + d] * (z / (1.f + __expf(-z)));
        yn[d] = g;
        ss += g * g;
    }
    red[tid] = ss; __syncthreads();
    for (int o = 128; o; o >>= 1) { if (tid < o) red[tid] += red[tid + o]; __syncthreads(); }
    float scale = rsqrtf(red[0] / (float)DI + EPS);
    for (int d = tid; d < DI; d += 256) yn[d] *= scale * norm_w[d];
    __syncthreads();
    for (int m = tid; m < DM; m += 256) {
        float accm = 0.f;
        for (int d = 0; d < DI; d++) accm = fmaf(yn[d], Wout[(size_t)d * DM + m], accm);
        seq[m] = accm;
    }
    __syncthreads();
    if (tid < NCLS) {
        float acc = bc[tid];
        for (int m = 0; m < DM; m++) acc = fmaf(seq[m], Wc[m * NCLS + tid], acc);
        out[b * NCLS + tid] = acc;
    }
}

// ---------------- launch -------------------------------------------------------
extern "C" void kernel_launch(void* const* d_in, const int* in_sizes, int n_in,
                              void* d_out, int out_size)
{
    const float* x       = (const float*)d_in[0];
    const float* W1      = (const float*)d_in[1];
    const float* b1      = (const float*)d_in[2];
    const float* W2      = (const float*)d_in[3];
    const float* b2      = (const float*)d_in[4];
    const float* W3      = (const float*)d_in[5];
    const float* b3      = (const float*)d_in[6];
    const float* Win     = (const float*)d_in[7];
    const float* conv_w  = (const float*)d_in[8];
    const float* conv_b  = (const float*)d_in[9];
    const float* dt_bias = (const float*)d_in[10];
    const float* A_log   = (const float*)d_in[11];
    const float* Dv      = (const float*)d_in[12];
    const float* norm_w  = (const float*)d_in[13];
    const float* Wout    = (const float*)d_in[14];
    const float* Wc      = (const float*)d_in[15];
    const float* bc      = (const float*)d_in[16];
    float* out = (float*)d_out;

    uint32_t *h2h, *uh, *w2f, *w3f, *winf;
    float *xbcr, *Bm, *Cm, *dtp, *beta, *wbuf, *yb, *zb;
    int *need;
    cudaGetSymbolAddress((void**)&h2h,  g_h2h);
    cudaGetSymbolAddress((void**)&uh,   g_uh);
    cudaGetSymbolAddress((void**)&w2f,  g_w2f);
    cudaGetSymbolAddress((void**)&w3f,  g_w3f);
    cudaGetSymbolAddress((void**)&winf, g_winf);
    cudaGetSymbolAddress((void**)&xbcr, g_xbcr);
    cudaGetSymbolAddress((void**)&Bm,   g_Bm);
    cudaGetSymbolAddress((void**)&Cm,   g_Cm);
    cudaGetSymbolAddress((void**)&dtp,  g_dtp);
    cudaGetSymbolAddress((void**)&beta, g_beta);
    cudaGetSymbolAddress((void**)&wbuf, g_wbuf);
    cudaGetSymbolAddress((void**)&need, g_need);
    cudaGetSymbolAddress((void**)&yb,   g_y);
    cudaGetSymbolAddress((void**)&zb,   g_z);

    static bool attr_done = false;
    if (!attr_done) {
        cudaFuncSetAttribute(hgemm_kernel<0,1>, cudaFuncAttributeMaxDynamicSharedMemorySize, SMEM_BYTES);
        cudaFuncSetAttribute(hgemm_kernel<0,0>, cudaFuncAttributeMaxDynamicSharedMemorySize, SMEM_BYTES);
        cudaFuncSetAttribute(g12_kernel, cudaFuncAttributeMaxDynamicSharedMemorySize, G12_SMEM);
        attr_done = true;
    }

    // weight packing (fragment-ordered fp16)
    prep_kernel<<<(WINF_WORDS + 255) / 256, 256>>>(W2, W3, Win);
    // fused G1+G2: x -> h2 (relu both, packed half2)
    g12_kernel<<<dim3(2, BL/128), 256, G12_SMEM>>>(x, W1, b1, w2f, b2, h2h);
    // G3: 256 -> 512 (NBLK=4)
    hgemm_kernel<0, 1><<<dim3(4, BL/128), 256, SMEM_BYTES>>>(
        h2h, 128, w3f, 4, b3, (float*)uh, 256, 512, 256, 0, nullptr);
    // G4a: B/C/dt columns (n-blocks 8..9, NBLK=10)
    hgemm_kernel<0, 0><<<dim3(2, BL/128), 256, SMEM_BYTES>>>(
        uh, 256, winf, 10, nullptr, xbcr, REST, REST, 512, 8, nullptr);
    // conv for B/C/dt channels
    conv_kernel<<<dim3(1, B_, L_/LCH), 192>>>(xbcr, conv_w, conv_b, dt_bias, Bm, Cm, dtp);
    // beta
    beta_kernel<<<BL/8, 256>>>(Bm, Cm, beta);
    // fused suffix scan + w + need flags
    scanw_kernel<<<B_*H_, 256>>>(dtp, A_log, beta, wbuf, need);
    // G4b: x columns (n-blocks 0..7), flag check inlined from need
    hgemm_kernel<0, 0><<<dim3(8, BL/128), 256, SMEM_BYTES>>>(
        uh, 256, winf, 10, nullptr, xbcr, REST, REST, 512, 0, need);
    // z GEMV at last position
    zv_kernel<<<dim3(8, B_), 128>>>(uh, Win, zb);
    // fused conv-x + y reduction with chunk + j-block skip
    xy_kernel<<<B_*H_, 512>>>(xbcr, conv_w, conv_b, wbuf, need, Dv, yb);
    // head
    final_kernel<<<B_, 256>>>(yb, zb, norm_w, Wout, Wc, bc, out);
    (void)in_sizes; (void)n_in; (void)out_size;
}